// round 3
// baseline (speedup 1.0000x reference)
#include <cuda_runtime.h>
#include <cstdint>

// Dendrite_54417235641041 — GB300 sm_103a
// y[b,d] = sum_{v=0..255} LWv[v] * prod_{i in bits(v)} t_i,  t_i = sigmoid(k*(w*x-q))[7-i]
// LWv[0] = lin_b (empty product), LWv[v] = lin_w[v-1].
// Per-thread: nibble-split subset-product DP + packed f32x2 bilinear with LW in shared.

#define THREADS 256
#define BPB 8  // b-values per block (one warp per b, 32 lanes = 32 d's)

__device__ __forceinline__ unsigned long long pk2(float lo, float hi) {
    unsigned long long r;
    asm("mov.b64 %0, {%1, %2};" : "=l"(r) : "f"(lo), "f"(hi));
    return r;
}
__device__ __forceinline__ void upk2(unsigned long long v, float& lo, float& hi) {
    asm("mov.b64 {%0, %1}, %2;" : "=f"(lo), "=f"(hi) : "l"(v));
}
__device__ __forceinline__ unsigned long long fma2(unsigned long long a,
                                                   unsigned long long b,
                                                   unsigned long long c) {
    unsigned long long r;
    asm("fma.rn.f32x2 %0, %1, %2, %3;" : "=l"(r) : "l"(a), "l"(b), "l"(c));
    return r;
}
__device__ __forceinline__ unsigned long long mul2_(unsigned long long a,
                                                    unsigned long long b) {
    unsigned long long r;
    asm("mul.rn.f32x2 %0, %1, %2;" : "=l"(r) : "l"(a), "l"(b));
    return r;
}

__global__ __launch_bounds__(THREADS)
void dendrite_kernel(const float* __restrict__ x,  const float* __restrict__ k,
                     const float* __restrict__ w,  const float* __restrict__ q,
                     const float* __restrict__ lin_w, const float* __restrict__ lin_b,
                     float* __restrict__ out)
{
    __shared__ __align__(16) float sA[256];   // k*w, [d*8+j]
    __shared__ __align__(16) float sC[256];   // k*q, [d*8+j]
    __shared__ __align__(16) float sLW[256];  // LWv: [0]=bias, [v]=lin_w[v-1]
    __shared__ __align__(16) float sX[BPB * 8];

    const int tid = threadIdx.x;

    // ---- cooperative load / precompute (256 threads, 256 coeffs) ----
    {
        float kk = k[tid];
        sA[tid] = kk * w[tid];
        sC[tid] = kk * q[tid];
        sLW[tid] = (tid == 0) ? lin_b[0] : lin_w[tid - 1];
        if (tid < BPB * 8) sX[tid] = x[blockIdx.x * (BPB * 8) + tid];
    }
    __syncthreads();

    const int d  = tid & 31;   // lane = d
    const int bl = tid >> 5;   // warp = local b

    // x (warp-broadcast) and per-d coefficients, vectorized shared reads
    float4 xa = *(const float4*)(sX + bl * 8);
    float4 xb = *(const float4*)(sX + bl * 8 + 4);
    float4 a0 = *(const float4*)(sA + d * 8);
    float4 a1 = *(const float4*)(sA + d * 8 + 4);
    float4 c0 = *(const float4*)(sC + d * 8);
    float4 c1 = *(const float4*)(sC + d * 8 + 4);
    float xv[8] = {xa.x, xa.y, xa.z, xa.w, xb.x, xb.y, xb.z, xb.w};
    float av[8] = {a0.x, a0.y, a0.z, a0.w, a1.x, a1.y, a1.z, a1.w};
    float cv[8] = {c0.x, c0.y, c0.z, c0.w, c1.x, c1.y, c1.z, c1.w};

    // ---- sigmoids: s_j = 1/(1+exp(-(k*w*x - k*q))) ----
    float s[8];
#pragma unroll
    for (int j = 0; j < 8; j++) {
        float z = fmaf(av[j], xv[j], -cv[j]);
        float e = __expf(-z);
        s[j] = __fdividef(1.0f, 1.0f + e);
    }

    // mask rows are MSB-first: bit i of v  <->  s[7-i]
    float t0 = s[7], t1 = s[6], t2 = s[5], t3 = s[4];  // low nibble vars
    float u0 = s[3], u1 = s[2], u2 = s[1], u3 = s[0];  // high nibble vars

    // ---- subset-product DP tables (11 FMUL each) ----
    float Plo[16], Phi[16];
    Plo[0] = 1.f;      Plo[1] = t0;          Plo[2] = t1;          Plo[3] = t1 * t0;
    Plo[4] = t2;       Plo[5] = t2 * t0;     Plo[6] = t2 * t1;     Plo[7] = t2 * Plo[3];
    Plo[8] = t3;       Plo[9] = t3 * t0;     Plo[10] = t3 * t1;    Plo[11] = t3 * Plo[3];
    Plo[12] = t3 * t2; Plo[13] = t3 * Plo[5];Plo[14] = t3 * Plo[6];Plo[15] = t3 * Plo[7];
    Phi[0] = 1.f;      Phi[1] = u0;          Phi[2] = u1;          Phi[3] = u1 * u0;
    Phi[4] = u2;       Phi[5] = u2 * u0;     Phi[6] = u2 * u1;     Phi[7] = u2 * Phi[3];
    Phi[8] = u3;       Phi[9] = u3 * u0;     Phi[10] = u3 * u1;    Phi[11] = u3 * Phi[3];
    Phi[12] = u3 * u2; Phi[13] = u3 * Phi[5];Phi[14] = u3 * Phi[6];Phi[15] = u3 * Phi[7];

    // pack Plo into 8 f32x2 operands
    unsigned long long plo2[8];
#pragma unroll
    for (int j = 0; j < 8; j++) plo2[j] = pk2(Plo[2 * j], Plo[2 * j + 1]);

    // ---- bilinear: y = sum_hi Phi[hi] * (LW row . Plo), packed f32x2 ----
    const uint32_t lwbase = (uint32_t)__cvta_generic_to_shared(sLW);
    float y = 0.0f;
#pragma unroll
    for (int hi = 0; hi < 16; hi++) {
        unsigned long long l0, l1, l2, l3, l4, l5, l6, l7;
        uint32_t a = lwbase + hi * 64;
        asm("ld.shared.v2.u64 {%0,%1}, [%2];" : "=l"(l0), "=l"(l1) : "r"(a));
        asm("ld.shared.v2.u64 {%0,%1}, [%2];" : "=l"(l2), "=l"(l3) : "r"(a + 16));
        asm("ld.shared.v2.u64 {%0,%1}, [%2];" : "=l"(l4), "=l"(l5) : "r"(a + 32));
        asm("ld.shared.v2.u64 {%0,%1}, [%2];" : "=l"(l6), "=l"(l7) : "r"(a + 48));
        unsigned long long acc = mul2_(l0, plo2[0]);
        acc = fma2(l1, plo2[1], acc);
        acc = fma2(l2, plo2[2], acc);
        acc = fma2(l3, plo2[3], acc);
        acc = fma2(l4, plo2[4], acc);
        acc = fma2(l5, plo2[5], acc);
        acc = fma2(l6, plo2[6], acc);
        acc = fma2(l7, plo2[7], acc);
        float rl, rh;
        upk2(acc, rl, rh);
        y = fmaf(Phi[hi], rl + rh, y);
    }

    const int b = blockIdx.x * BPB + bl;
    out[b * 32 + d] = y;   // output layout [B,1,D] -> b*D + d
}

extern "C" void kernel_launch(void* const* d_in, const int* in_sizes, int n_in,
                              void* d_out, int out_size)
{
    const float* x     = (const float*)d_in[0];
    const float* k     = (const float*)d_in[1];
    const float* w     = (const float*)d_in[2];
    const float* q     = (const float*)d_in[3];
    // d_in[4] = mask: unused — its structure (binary expansion of 1..255,
    // MSB-first) is baked into the subset-product formulation above.
    const float* lin_w = (const float*)d_in[5];
    const float* lin_b = (const float*)d_in[6];
    float* out = (float*)d_out;

    // B=8192, D=32 -> 262144 threads; 8 b's per 256-thread block -> 1024 blocks
    dendrite_kernel<<<8192 / BPB, THREADS>>>(x, k, w, q, lin_w, lin_b, out);
}

// round 4
// speedup vs baseline: 1.0030x; 1.0030x over previous
#include <cuda_runtime.h>
#include <cstdint>

// Dendrite_54417235641041 — GB300 sm_103a
// y[b,d] = sum_{v=0..255} LWv[v] * prod_{i in bits(v)} t_i,  t_i = sigmoid(k*(w*x-q))[7-i]
// LWv[0] = lin_b (empty product), LWv[v] = lin_w[v-1].
// Nibble-split subset-product DP + packed f32x2 bilinear; each thread computes
// TWO (b,d) outputs (same d, adjacent b) so the shared LW stream is amortized 2x.

#define THREADS 256
#define BPB 16  // b-values per block (8 warps x 2 b each; lane = d)

__device__ __forceinline__ unsigned long long pk2(float lo, float hi) {
    unsigned long long r;
    asm("mov.b64 %0, {%1, %2};" : "=l"(r) : "f"(lo), "f"(hi));
    return r;
}
__device__ __forceinline__ void upk2(unsigned long long v, float& lo, float& hi) {
    asm("mov.b64 {%0, %1}, %2;" : "=f"(lo), "=f"(hi) : "l"(v));
}
__device__ __forceinline__ unsigned long long fma2(unsigned long long a,
                                                   unsigned long long b,
                                                   unsigned long long c) {
    unsigned long long r;
    asm("fma.rn.f32x2 %0, %1, %2, %3;" : "=l"(r) : "l"(a), "l"(b), "l"(c));
    return r;
}
__device__ __forceinline__ unsigned long long mul2_(unsigned long long a,
                                                    unsigned long long b) {
    unsigned long long r;
    asm("mul.rn.f32x2 %0, %1, %2;" : "=l"(r) : "l"(a), "l"(b));
    return r;
}

struct DP {
    unsigned long long plo2[8];  // packed low-nibble subset products
    float Phi[16];               // high-nibble subset products
};

__device__ __forceinline__ void build_dp(const float s[8], DP& o) {
    // mask rows are MSB-first: bit i of v  <->  s[7-i]
    float t0 = s[7], t1 = s[6], t2 = s[5], t3 = s[4];  // low nibble vars
    float u0 = s[3], u1 = s[2], u2 = s[1], u3 = s[0];  // high nibble vars

    float Plo[16];
    Plo[0] = 1.f;      Plo[1] = t0;           Plo[2] = t1;           Plo[3] = t1 * t0;
    Plo[4] = t2;       Plo[5] = t2 * t0;      Plo[6] = t2 * t1;      Plo[7] = t2 * Plo[3];
    Plo[8] = t3;       Plo[9] = t3 * t0;      Plo[10] = t3 * t1;     Plo[11] = t3 * Plo[3];
    Plo[12] = t3 * t2; Plo[13] = t3 * Plo[5]; Plo[14] = t3 * Plo[6]; Plo[15] = t3 * Plo[7];
#pragma unroll
    for (int j = 0; j < 8; j++) o.plo2[j] = pk2(Plo[2 * j], Plo[2 * j + 1]);

    o.Phi[0] = 1.f;      o.Phi[1] = u0;             o.Phi[2] = u1;             o.Phi[3] = u1 * u0;
    o.Phi[4] = u2;       o.Phi[5] = u2 * u0;        o.Phi[6] = u2 * u1;        o.Phi[7] = u2 * o.Phi[3];
    o.Phi[8] = u3;       o.Phi[9] = u3 * u0;        o.Phi[10] = u3 * u1;       o.Phi[11] = u3 * o.Phi[3];
    o.Phi[12] = u3 * u2; o.Phi[13] = u3 * o.Phi[5]; o.Phi[14] = u3 * o.Phi[6]; o.Phi[15] = u3 * o.Phi[7];
}

__global__ __launch_bounds__(THREADS)
void dendrite_kernel(const float* __restrict__ x,  const float* __restrict__ k,
                     const float* __restrict__ w,  const float* __restrict__ q,
                     const float* __restrict__ lin_w, const float* __restrict__ lin_b,
                     float* __restrict__ out)
{
    __shared__ __align__(16) float sA[256];       // k*w, [d*8+j]
    __shared__ __align__(16) float sC[256];       // k*q, [d*8+j]
    __shared__ __align__(16) float sLW[256];      // LWv: [0]=bias, [v]=lin_w[v-1]
    __shared__ __align__(16) float sX[BPB * 8];

    const int tid = threadIdx.x;

    // ---- cooperative load / precompute ----
    {
        float kk = k[tid];
        sA[tid] = kk * w[tid];
        sC[tid] = kk * q[tid];
        sLW[tid] = (tid == 0) ? lin_b[0] : lin_w[tid - 1];
        if (tid < BPB * 8) sX[tid] = x[blockIdx.x * (BPB * 8) + tid];
    }
    __syncthreads();

    const int d  = tid & 31;   // lane = d
    const int bl = tid >> 5;   // warp = local b-pair index

    // per-d sigmoid coefficients (shared between both b's of this thread)
    float4 a0 = *(const float4*)(sA + d * 8);
    float4 a1 = *(const float4*)(sA + d * 8 + 4);
    float4 c0 = *(const float4*)(sC + d * 8);
    float4 c1 = *(const float4*)(sC + d * 8 + 4);
    float av[8] = {a0.x, a0.y, a0.z, a0.w, a1.x, a1.y, a1.z, a1.w};
    float cv[8] = {c0.x, c0.y, c0.z, c0.w, c1.x, c1.y, c1.z, c1.w};

    // two x rows (warp-broadcast shared reads)
    float4 xa0 = *(const float4*)(sX + bl * 16);
    float4 xb0 = *(const float4*)(sX + bl * 16 + 4);
    float4 xa1 = *(const float4*)(sX + bl * 16 + 8);
    float4 xb1 = *(const float4*)(sX + bl * 16 + 12);
    float xv0[8] = {xa0.x, xa0.y, xa0.z, xa0.w, xb0.x, xb0.y, xb0.z, xb0.w};
    float xv1[8] = {xa1.x, xa1.y, xa1.z, xa1.w, xb1.x, xb1.y, xb1.z, xb1.w};

    // ---- sigmoids for both b's ----
    float s0[8], s1[8];
#pragma unroll
    for (int j = 0; j < 8; j++) {
        float z0 = fmaf(av[j], xv0[j], -cv[j]);
        float z1 = fmaf(av[j], xv1[j], -cv[j]);
        s0[j] = __fdividef(1.0f, 1.0f + __expf(-z0));
        s1[j] = __fdividef(1.0f, 1.0f + __expf(-z1));
    }

    DP p0, p1;
    build_dp(s0, p0);
    build_dp(s1, p1);

    // ---- bilinear: one LW stream feeds two independent packed dot chains ----
    const uint32_t lwbase = (uint32_t)__cvta_generic_to_shared(sLW);
    unsigned long long y2_0 = 0ull, y2_1 = 0ull;
#pragma unroll
    for (int hi = 0; hi < 16; hi++) {
        unsigned long long l0, l1, l2, l3, l4, l5, l6, l7;
        uint32_t a = lwbase + hi * 64;
        asm("ld.shared.v2.u64 {%0,%1}, [%2];" : "=l"(l0), "=l"(l1) : "r"(a));
        asm("ld.shared.v2.u64 {%0,%1}, [%2];" : "=l"(l2), "=l"(l3) : "r"(a + 16));
        asm("ld.shared.v2.u64 {%0,%1}, [%2];" : "=l"(l4), "=l"(l5) : "r"(a + 32));
        asm("ld.shared.v2.u64 {%0,%1}, [%2];" : "=l"(l6), "=l"(l7) : "r"(a + 48));

        unsigned long long acc0 = mul2_(l0, p0.plo2[0]);
        unsigned long long acc1 = mul2_(l0, p1.plo2[0]);
        acc0 = fma2(l1, p0.plo2[1], acc0);  acc1 = fma2(l1, p1.plo2[1], acc1);
        acc0 = fma2(l2, p0.plo2[2], acc0);  acc1 = fma2(l2, p1.plo2[2], acc1);
        acc0 = fma2(l3, p0.plo2[3], acc0);  acc1 = fma2(l3, p1.plo2[3], acc1);
        acc0 = fma2(l4, p0.plo2[4], acc0);  acc1 = fma2(l4, p1.plo2[4], acc1);
        acc0 = fma2(l5, p0.plo2[5], acc0);  acc1 = fma2(l5, p1.plo2[5], acc1);
        acc0 = fma2(l6, p0.plo2[6], acc0);  acc1 = fma2(l6, p1.plo2[6], acc1);
        acc0 = fma2(l7, p0.plo2[7], acc0);  acc1 = fma2(l7, p1.plo2[7], acc1);

        y2_0 = fma2(pk2(p0.Phi[hi], p0.Phi[hi]), acc0, y2_0);
        y2_1 = fma2(pk2(p1.Phi[hi], p1.Phi[hi]), acc1, y2_1);
    }

    float y0l, y0h, y1l, y1h;
    upk2(y2_0, y0l, y0h);
    upk2(y2_1, y1l, y1h);

    const int b0 = blockIdx.x * BPB + bl * 2;
    out[b0 * 32 + d]       = y0l + y0h;   // output layout [B,1,D] -> b*D + d
    out[(b0 + 1) * 32 + d] = y1l + y1h;
}

extern "C" void kernel_launch(void* const* d_in, const int* in_sizes, int n_in,
                              void* d_out, int out_size)
{
    const float* x     = (const float*)d_in[0];
    const float* k     = (const float*)d_in[1];
    const float* w     = (const float*)d_in[2];
    const float* q     = (const float*)d_in[3];
    // d_in[4] = mask: unused — its structure (binary expansion of 1..255,
    // MSB-first) is baked into the subset-product formulation above.
    const float* lin_w = (const float*)d_in[5];
    const float* lin_b = (const float*)d_in[6];
    float* out = (float*)d_out;

    // B=8192, D=32; 16 b's per 256-thread block -> 512 blocks, 2 (b,d) per thread
    dendrite_kernel<<<8192 / BPB, THREADS>>>(x, k, w, q, lin_w, lin_b, out);
}

// round 7
// speedup vs baseline: 1.0060x; 1.0030x over previous
#include <cuda_runtime.h>
#include <cstdint>

// Dendrite_54417235641041 — GB300 sm_103a
// y[b,d] = sum_{v=0..255} LWv[v] * prod_{i in bits(v)} t_i,  t_i = sigmoid(k*(w*x-q))[7-i]
// LWv[0] = lin_b (empty product), LWv[v] = lin_w[v-1].
// Nibble-split subset-product DP + packed f32x2 bilinear; 2 (b,d) per thread.
// R5: launch_bounds(256,4) -> regs<=64 -> 4 blocks/SM -> grid 512 fully resident
// in ONE wave. Phi factored as PA[hi>>2]*PB[hi&3] to cut 32 regs; sigmoid uses
// log2e-folded coefficients (FFMA+EX2+FADD+RCP).

#define THREADS 256
#define BPB 16  // b-values per block (8 warps x 2 b each; lane = d)

__device__ __forceinline__ unsigned long long pk2(float lo, float hi) {
    unsigned long long r;
    asm("mov.b64 %0, {%1, %2};" : "=l"(r) : "f"(lo), "f"(hi));
    return r;
}
__device__ __forceinline__ void upk2(unsigned long long v, float& lo, float& hi) {
    asm("mov.b64 {%0, %1}, %2;" : "=f"(lo), "=f"(hi) : "l"(v));
}
__device__ __forceinline__ unsigned long long fma2(unsigned long long a,
                                                   unsigned long long b,
                                                   unsigned long long c) {
    unsigned long long r;
    asm("fma.rn.f32x2 %0, %1, %2, %3;" : "=l"(r) : "l"(a), "l"(b), "l"(c));
    return r;
}
__device__ __forceinline__ unsigned long long mul2_(unsigned long long a,
                                                    unsigned long long b) {
    unsigned long long r;
    asm("mul.rn.f32x2 %0, %1, %2;" : "=l"(r) : "l"(a), "l"(b));
    return r;
}
__device__ __forceinline__ float ex2_(float x) {
    float r; asm("ex2.approx.f32 %0, %1;" : "=f"(r) : "f"(x)); return r;
}
__device__ __forceinline__ float rcp_(float x) {
    float r; asm("rcp.approx.f32 %0, %1;" : "=f"(r) : "f"(x)); return r;
}

struct DP {
    unsigned long long plo2[8];  // packed low-nibble subset products
    float PA[4];                 // high-nibble: bits 2,3 (u2,u3)
    float PB[4];                 // high-nibble: bits 0,1 (u0,u1)
};

__device__ __forceinline__ void build_dp(const float s[8], DP& o) {
    // mask rows are MSB-first: bit i of v  <->  s[7-i]
    float t0 = s[7], t1 = s[6], t2 = s[5], t3 = s[4];  // low nibble vars
    float u0 = s[3], u1 = s[2], u2 = s[1], u3 = s[0];  // high nibble vars

    float Plo[16];
    Plo[0] = 1.f;      Plo[1] = t0;           Plo[2] = t1;           Plo[3] = t1 * t0;
    Plo[4] = t2;       Plo[5] = t2 * t0;      Plo[6] = t2 * t1;      Plo[7] = t2 * Plo[3];
    Plo[8] = t3;       Plo[9] = t3 * t0;      Plo[10] = t3 * t1;     Plo[11] = t3 * Plo[3];
    Plo[12] = t3 * t2; Plo[13] = t3 * Plo[5]; Plo[14] = t3 * Plo[6]; Plo[15] = t3 * Plo[7];
#pragma unroll
    for (int j = 0; j < 8; j++) o.plo2[j] = pk2(Plo[2 * j], Plo[2 * j + 1]);

    o.PB[0] = 1.f; o.PB[1] = u0; o.PB[2] = u1; o.PB[3] = u1 * u0;
    o.PA[0] = 1.f; o.PA[1] = u2; o.PA[2] = u3; o.PA[3] = u3 * u2;
}

__global__ __launch_bounds__(THREADS, 4)
void dendrite_kernel(const float* __restrict__ x,  const float* __restrict__ k,
                     const float* __restrict__ w,  const float* __restrict__ q,
                     const float* __restrict__ lin_w, const float* __restrict__ lin_b,
                     float* __restrict__ out)
{
    __shared__ __align__(16) float sA[256];       // -k*w*log2e, [d*8+j]
    __shared__ __align__(16) float sC[256];       //  k*q*log2e, [d*8+j]
    __shared__ __align__(16) float sLW[256];      // LWv: [0]=bias, [v]=lin_w[v-1]
    __shared__ __align__(16) float sX[BPB * 8];

    const int tid = threadIdx.x;
    const float LOG2E = 1.4426950408889634f;

    // ---- cooperative load / precompute ----
    {
        float kk = k[tid] * LOG2E;
        sA[tid] = -kk * w[tid];
        sC[tid] =  kk * q[tid];
        sLW[tid] = (tid == 0) ? lin_b[0] : lin_w[tid - 1];
        if (tid < BPB * 8) sX[tid] = x[blockIdx.x * (BPB * 8) + tid];
    }
    __syncthreads();

    const int d  = tid & 31;   // lane = d
    const int bl = tid >> 5;   // warp = local b-pair index

    // per-d sigmoid coefficients (shared between both b's of this thread)
    float4 a0 = *(const float4*)(sA + d * 8);
    float4 a1 = *(const float4*)(sA + d * 8 + 4);
    float4 c0 = *(const float4*)(sC + d * 8);
    float4 c1 = *(const float4*)(sC + d * 8 + 4);
    float av[8] = {a0.x, a0.y, a0.z, a0.w, a1.x, a1.y, a1.z, a1.w};
    float cv[8] = {c0.x, c0.y, c0.z, c0.w, c1.x, c1.y, c1.z, c1.w};

    // two x rows (warp-broadcast shared reads)
    float4 xa0 = *(const float4*)(sX + bl * 16);
    float4 xb0 = *(const float4*)(sX + bl * 16 + 4);
    float4 xa1 = *(const float4*)(sX + bl * 16 + 8);
    float4 xb1 = *(const float4*)(sX + bl * 16 + 12);
    float xv0[8] = {xa0.x, xa0.y, xa0.z, xa0.w, xb0.x, xb0.y, xb0.z, xb0.w};
    float xv1[8] = {xa1.x, xa1.y, xa1.z, xa1.w, xb1.x, xb1.y, xb1.z, xb1.w};

    // ---- sigmoids: s = 1/(1 + 2^(A*x + C)), A=-k*w*log2e, C=k*q*log2e ----
    float s0[8], s1[8];
#pragma unroll
    for (int j = 0; j < 8; j++) {
        float e0 = ex2_(fmaf(av[j], xv0[j], cv[j]));
        float e1 = ex2_(fmaf(av[j], xv1[j], cv[j]));
        s0[j] = rcp_(1.0f + e0);
        s1[j] = rcp_(1.0f + e1);
    }

    DP p0, p1;
    build_dp(s0, p0);
    build_dp(s1, p1);

    // ---- bilinear: one LW stream feeds two independent packed dot chains ----
    const uint32_t lwbase = (uint32_t)__cvta_generic_to_shared(sLW);
    float y0 = 0.0f, y1 = 0.0f;
#pragma unroll
    for (int hi = 0; hi < 16; hi++) {
        const int h0 = hi & 3, h1 = hi >> 2;
        unsigned long long l0, l1, l2, l3, l4, l5, l6, l7;
        uint32_t a = lwbase + hi * 64;
        asm("ld.shared.v2.u64 {%0,%1}, [%2];" : "=l"(l0), "=l"(l1) : "r"(a));
        asm("ld.shared.v2.u64 {%0,%1}, [%2];" : "=l"(l2), "=l"(l3) : "r"(a + 16));

        unsigned long long acc0 = mul2_(l0, p0.plo2[0]);
        unsigned long long acc1 = mul2_(l0, p1.plo2[0]);
        acc0 = fma2(l1, p0.plo2[1], acc0);  acc1 = fma2(l1, p1.plo2[1], acc1);
        acc0 = fma2(l2, p0.plo2[2], acc0);  acc1 = fma2(l2, p1.plo2[2], acc1);
        acc0 = fma2(l3, p0.plo2[3], acc0);  acc1 = fma2(l3, p1.plo2[3], acc1);

        asm("ld.shared.v2.u64 {%0,%1}, [%2];" : "=l"(l4), "=l"(l5) : "r"(a + 32));
        asm("ld.shared.v2.u64 {%0,%1}, [%2];" : "=l"(l6), "=l"(l7) : "r"(a + 48));
        acc0 = fma2(l4, p0.plo2[4], acc0);  acc1 = fma2(l4, p1.plo2[4], acc1);
        acc0 = fma2(l5, p0.plo2[5], acc0);  acc1 = fma2(l5, p1.plo2[5], acc1);
        acc0 = fma2(l6, p0.plo2[6], acc0);  acc1 = fma2(l6, p1.plo2[6], acc1);
        acc0 = fma2(l7, p0.plo2[7], acc0);  acc1 = fma2(l7, p1.plo2[7], acc1);

        float r0l, r0h, r1l, r1h;
        upk2(acc0, r0l, r0h);
        upk2(acc1, r1l, r1h);
        // Phi[hi] = PA[h1]*PB[h0]; PA[0]=PB[0]=1 fold at compile time
        y0 = fmaf(p0.PA[h1] * p0.PB[h0], r0l + r0h, y0);
        y1 = fmaf(p1.PA[h1] * p1.PB[h0], r1l + r1h, y1);
    }

    const int b0 = blockIdx.x * BPB + bl * 2;
    out[b0 * 32 + d]       = y0;   // output layout [B,1,D] -> b*D + d
    out[(b0 + 1) * 32 + d] = y1;
}

extern "C" void kernel_launch(void* const* d_in, const int* in_sizes, int n_in,
                              void* d_out, int out_size)
{
    const float* x     = (const float*)d_in[0];
    const float* k     = (const float*)d_in[1];
    const float* w     = (const float*)d_in[2];
    const float* q     = (const float*)d_in[3];
    // d_in[4] = mask: unused — its structure (binary expansion of 1..255,
    // MSB-first) is baked into the subset-product formulation above.
    const float* lin_w = (const float*)d_in[5];
    const float* lin_b = (const float*)d_in[6];
    float* out = (float*)d_out;

    // B=8192, D=32; 16 b's per 256-thread block -> 512 blocks, 2 (b,d) per thread
    // 4 blocks/SM residency (launch_bounds) -> all 512 blocks in one wave.
    dendrite_kernel<<<8192 / BPB, THREADS>>>(x, k, w, q, lin_w, lin_b, out);
}

// round 11
// speedup vs baseline: 1.0340x; 1.0278x over previous
#include <cuda_runtime.h>
#include <cstdint>

// Dendrite_54417235641041 — GB300 sm_103a
// y[b,d] = sum_{v=0..255} LWv[v] * prod_{i in bits(v)} t_i,  t_i = sigmoid(k*(w*x-q))[7-i]
// LWv[0] = lin_b (empty product), LWv[v] = lin_w[v-1].
// Nibble-split subset-product DP + packed f32x2 bilinear.
// R8: FOUR (b,d) outputs per thread (same d, 4 adjacent b). One LW row load
// (4x LDS.128) feeds four independent packed FMA chains -> 4-way ILP, 16
// LDS per output (was 32). Phi factored PA[hi>>2]*PB[hi&3], PA0=PB0=1 folded.

#define THREADS 256
#define BPB 32  // b-values per block: 8 warps x 4 b each; lane = d

__device__ __forceinline__ unsigned long long pk2(float lo, float hi) {
    unsigned long long r;
    asm("mov.b64 %0, {%1, %2};" : "=l"(r) : "f"(lo), "f"(hi));
    return r;
}
__device__ __forceinline__ void upk2(unsigned long long v, float& lo, float& hi) {
    asm("mov.b64 {%0, %1}, %2;" : "=f"(lo), "=f"(hi) : "l"(v));
}
__device__ __forceinline__ unsigned long long fma2(unsigned long long a,
                                                   unsigned long long b,
                                                   unsigned long long c) {
    unsigned long long r;
    asm("fma.rn.f32x2 %0, %1, %2, %3;" : "=l"(r) : "l"(a), "l"(b), "l"(c));
    return r;
}
__device__ __forceinline__ unsigned long long mul2_(unsigned long long a,
                                                    unsigned long long b) {
    unsigned long long r;
    asm("mul.rn.f32x2 %0, %1, %2;" : "=l"(r) : "l"(a), "l"(b));
    return r;
}
__device__ __forceinline__ float ex2_(float x) {
    float r; asm("ex2.approx.f32 %0, %1;" : "=f"(r) : "f"(x)); return r;
}
__device__ __forceinline__ float rcp_(float x) {
    float r; asm("rcp.approx.f32 %0, %1;" : "=f"(r) : "f"(x)); return r;
}

// i is compile-time after full unroll; i==0 selects 1.0f so the multiply folds.
__device__ __forceinline__ float sel4(float v1, float v2, float v3, int i) {
    return i == 0 ? 1.0f : (i == 1 ? v1 : (i == 2 ? v2 : v3));
}

struct Chain {
    unsigned long long plo2[8];      // packed low-nibble subset products
    float pa1, pa2, pa3;             // PA[1..3] (PA[0]=1 implicit)
    float pb1, pb2, pb3;             // PB[1..3] (PB[0]=1 implicit)
};

__device__ __forceinline__ void build_chain(const float s[8], Chain& o) {
    // mask rows are MSB-first: bit i of v  <->  s[7-i]
    float t0 = s[7], t1 = s[6], t2 = s[5], t3 = s[4];  // low nibble vars
    float u0 = s[3], u1 = s[2], u2 = s[1], u3 = s[0];  // high nibble vars

    float Plo[16];
    Plo[0] = 1.f;      Plo[1] = t0;           Plo[2] = t1;           Plo[3] = t1 * t0;
    Plo[4] = t2;       Plo[5] = t2 * t0;      Plo[6] = t2 * t1;      Plo[7] = t2 * Plo[3];
    Plo[8] = t3;       Plo[9] = t3 * t0;      Plo[10] = t3 * t1;     Plo[11] = t3 * Plo[3];
    Plo[12] = t3 * t2; Plo[13] = t3 * Plo[5]; Plo[14] = t3 * Plo[6]; Plo[15] = t3 * Plo[7];
#pragma unroll
    for (int j = 0; j < 8; j++) o.plo2[j] = pk2(Plo[2 * j], Plo[2 * j + 1]);

    o.pb1 = u0; o.pb2 = u1; o.pb3 = u1 * u0;
    o.pa1 = u2; o.pa2 = u3; o.pa3 = u3 * u2;
}

__global__ __launch_bounds__(THREADS, 2)
void dendrite_kernel(const float* __restrict__ x,  const float* __restrict__ k,
                     const float* __restrict__ w,  const float* __restrict__ q,
                     const float* __restrict__ lin_w, const float* __restrict__ lin_b,
                     float* __restrict__ out)
{
    __shared__ __align__(16) float sA[256];       // -k*w*log2e, [d*8+j]
    __shared__ __align__(16) float sC[256];       //  k*q*log2e, [d*8+j]
    __shared__ __align__(16) float sLW[256];      // LWv: [0]=bias, [v]=lin_w[v-1]
    __shared__ __align__(16) float sX[BPB * 8];   // 256 floats

    const int tid = threadIdx.x;
    const float LOG2E = 1.4426950408889634f;

    // ---- cooperative load / precompute (256 threads cover all tables) ----
    {
        float kk = k[tid] * LOG2E;
        sA[tid] = -kk * w[tid];
        sC[tid] =  kk * q[tid];
        sLW[tid] = (tid == 0) ? lin_b[0] : lin_w[tid - 1];
        sX[tid] = x[blockIdx.x * (BPB * 8) + tid];
    }
    __syncthreads();

    const int d  = tid & 31;   // lane = d
    const int bl = tid >> 5;   // warp = local 4-b group

    // per-d sigmoid coefficients (shared by all 4 b's of this thread)
    float4 a0 = *(const float4*)(sA + d * 8);
    float4 a1 = *(const float4*)(sA + d * 8 + 4);
    float4 c0 = *(const float4*)(sC + d * 8);
    float4 c1 = *(const float4*)(sC + d * 8 + 4);
    float av[8] = {a0.x, a0.y, a0.z, a0.w, a1.x, a1.y, a1.z, a1.w};
    float cv[8] = {c0.x, c0.y, c0.z, c0.w, c1.x, c1.y, c1.z, c1.w};

    // ---- sigmoids + DP for 4 b's: s = 1/(1 + 2^(A*x + C)) ----
    Chain ch0, ch1, ch2, ch3;
#define MAKE_CHAIN(CH, IDX)                                                    \
    {                                                                          \
        const float* xr = sX + bl * 32 + (IDX) * 8;                            \
        float4 xA = *(const float4*)(xr);                                      \
        float4 xB = *(const float4*)(xr + 4);                                  \
        float xv[8] = {xA.x, xA.y, xA.z, xA.w, xB.x, xB.y, xB.z, xB.w};        \
        float s[8];                                                            \
        _Pragma("unroll")                                                      \
        for (int j = 0; j < 8; j++)                                            \
            s[j] = rcp_(1.0f + ex2_(fmaf(av[j], xv[j], cv[j])));               \
        build_chain(s, CH);                                                    \
    }
    MAKE_CHAIN(ch0, 0)
    MAKE_CHAIN(ch1, 1)
    MAKE_CHAIN(ch2, 2)
    MAKE_CHAIN(ch3, 3)
#undef MAKE_CHAIN

    // ---- bilinear: one LW row load feeds 4 independent packed dot chains ----
    const uint32_t lwbase = (uint32_t)__cvta_generic_to_shared(sLW);
    float y0 = 0.0f, y1 = 0.0f, y2 = 0.0f, y3 = 0.0f;
#pragma unroll
    for (int hi = 0; hi < 16; hi++) {
        const int h0 = hi & 3, h1 = hi >> 2;
        unsigned long long l0, l1, l2, l3, l4, l5, l6, l7;
        uint32_t a = lwbase + hi * 64;
        asm("ld.shared.v2.u64 {%0,%1}, [%2];" : "=l"(l0), "=l"(l1) : "r"(a));
        asm("ld.shared.v2.u64 {%0,%1}, [%2];" : "=l"(l2), "=l"(l3) : "r"(a + 16));
        asm("ld.shared.v2.u64 {%0,%1}, [%2];" : "=l"(l4), "=l"(l5) : "r"(a + 32));
        asm("ld.shared.v2.u64 {%0,%1}, [%2];" : "=l"(l6), "=l"(l7) : "r"(a + 48));

        unsigned long long A0 = mul2_(l0, ch0.plo2[0]);
        unsigned long long A1 = mul2_(l0, ch1.plo2[0]);
        unsigned long long A2 = mul2_(l0, ch2.plo2[0]);
        unsigned long long A3 = mul2_(l0, ch3.plo2[0]);
#pragma unroll
        for (int j = 1; j < 8; j++) {
            unsigned long long lj = (j == 1) ? l1 : (j == 2) ? l2 : (j == 3) ? l3
                                  : (j == 4) ? l4 : (j == 5) ? l5 : (j == 6) ? l6 : l7;
            A0 = fma2(lj, ch0.plo2[j], A0);
            A1 = fma2(lj, ch1.plo2[j], A1);
            A2 = fma2(lj, ch2.plo2[j], A2);
            A3 = fma2(lj, ch3.plo2[j], A3);
        }

        float rl, rh;
        upk2(A0, rl, rh);
        y0 = fmaf(sel4(ch0.pa1, ch0.pa2, ch0.pa3, h1) * sel4(ch0.pb1, ch0.pb2, ch0.pb3, h0),
                  rl + rh, y0);
        upk2(A1, rl, rh);
        y1 = fmaf(sel4(ch1.pa1, ch1.pa2, ch1.pa3, h1) * sel4(ch1.pb1, ch1.pb2, ch1.pb3, h0),
                  rl + rh, y1);
        upk2(A2, rl, rh);
        y2 = fmaf(sel4(ch2.pa1, ch2.pa2, ch2.pa3, h1) * sel4(ch2.pb1, ch2.pb2, ch2.pb3, h0),
                  rl + rh, y2);
        upk2(A3, rl, rh);
        y3 = fmaf(sel4(ch3.pa1, ch3.pa2, ch3.pa3, h1) * sel4(ch3.pb1, ch3.pb2, ch3.pb3, h0),
                  rl + rh, y3);
    }

    const int b0 = blockIdx.x * BPB + bl * 4;
    out[(b0 + 0) * 32 + d] = y0;   // output layout [B,1,D] -> b*D + d
    out[(b0 + 1) * 32 + d] = y1;
    out[(b0 + 2) * 32 + d] = y2;
    out[(b0 + 3) * 32 + d] = y3;
}

extern "C" void kernel_launch(void* const* d_in, const int* in_sizes, int n_in,
                              void* d_out, int out_size)
{
    const float* x     = (const float*)d_in[0];
    const float* k     = (const float*)d_in[1];
    const float* w     = (const float*)d_in[2];
    const float* q     = (const float*)d_in[3];
    // d_in[4] = mask: unused — its structure (binary expansion of 1..255,
    // MSB-first) is baked into the subset-product formulation above.
    const float* lin_w = (const float*)d_in[5];
    const float* lin_b = (const float*)d_in[6];
    float* out = (float*)d_out;

    // B=8192, D=32; 32 b's per 256-thread block -> 256 blocks, 4 (b,d)/thread.
    dendrite_kernel<<<8192 / BPB, THREADS>>>(x, k, w, q, lin_w, lin_b, out);
}

// round 12
// speedup vs baseline: 1.2271x; 1.1868x over previous
#include <cuda_runtime.h>
#include <cstdint>

// Dendrite_54417235641041 — GB300 sm_103a
// y[b,d] = sum_{v=0..255} LWv[v] * prod_{i in bits(v)} t_i,  t_i = sigmoid(k*(w*x-q))[7-i]
// LWv[0] = lin_b (empty product), LWv[v] = lin_w[v-1].
// Nibble-split subset-product DP + packed f32x2 bilinear; 2 (b,d) per thread.
// R12: occupancy play — 128-thread blocks, launch_bounds(128,8) -> regs<=64 ->
// 8 blocks/SM -> 8 warps/SMSP (latency hiding), grid=1024 small blocks for
// near-perfect SM load balance. Packed-phi tail (one unpack at the end).

#define THREADS 128
#define BPB 8   // b-values per block: 4 warps x 2 b each; lane = d

__device__ __forceinline__ unsigned long long pk2(float lo, float hi) {
    unsigned long long r;
    asm("mov.b64 %0, {%1, %2};" : "=l"(r) : "f"(lo), "f"(hi));
    return r;
}
__device__ __forceinline__ void upk2(unsigned long long v, float& lo, float& hi) {
    asm("mov.b64 {%0, %1}, %2;" : "=f"(lo), "=f"(hi) : "l"(v));
}
__device__ __forceinline__ unsigned long long fma2(unsigned long long a,
                                                   unsigned long long b,
                                                   unsigned long long c) {
    unsigned long long r;
    asm("fma.rn.f32x2 %0, %1, %2, %3;" : "=l"(r) : "l"(a), "l"(b), "l"(c));
    return r;
}
__device__ __forceinline__ unsigned long long mul2_(unsigned long long a,
                                                    unsigned long long b) {
    unsigned long long r;
    asm("mul.rn.f32x2 %0, %1, %2;" : "=l"(r) : "l"(a), "l"(b));
    return r;
}
__device__ __forceinline__ float ex2_(float x) {
    float r; asm("ex2.approx.f32 %0, %1;" : "=f"(r) : "f"(x)); return r;
}
__device__ __forceinline__ float rcp_(float x) {
    float r; asm("rcp.approx.f32 %0, %1;" : "=f"(r) : "f"(x)); return r;
}

// i is compile-time after full unroll; i==0 selects 1.0f so multiplies fold.
__device__ __forceinline__ float sel4(float v1, float v2, float v3, int i) {
    return i == 0 ? 1.0f : (i == 1 ? v1 : (i == 2 ? v2 : v3));
}

struct Chain {
    unsigned long long plo2[8];      // packed low-nibble subset products
    float pa1, pa2, pa3;             // PA[1..3] (PA[0]=1 implicit)  (u2,u3)
    float pb1, pb2, pb3;             // PB[1..3] (PB[0]=1 implicit)  (u0,u1)
};

__device__ __forceinline__ void build_chain(const float s[8], Chain& o) {
    // mask rows are MSB-first: bit i of v  <->  s[7-i]
    float t0 = s[7], t1 = s[6], t2 = s[5], t3 = s[4];  // low nibble vars
    float u0 = s[3], u1 = s[2], u2 = s[1], u3 = s[0];  // high nibble vars

    float Plo[16];
    Plo[0] = 1.f;      Plo[1] = t0;           Plo[2] = t1;           Plo[3] = t1 * t0;
    Plo[4] = t2;       Plo[5] = t2 * t0;      Plo[6] = t2 * t1;      Plo[7] = t2 * Plo[3];
    Plo[8] = t3;       Plo[9] = t3 * t0;      Plo[10] = t3 * t1;     Plo[11] = t3 * Plo[3];
    Plo[12] = t3 * t2; Plo[13] = t3 * Plo[5]; Plo[14] = t3 * Plo[6]; Plo[15] = t3 * Plo[7];
#pragma unroll
    for (int j = 0; j < 8; j++) o.plo2[j] = pk2(Plo[2 * j], Plo[2 * j + 1]);

    o.pb1 = u0; o.pb2 = u1; o.pb3 = u1 * u0;
    o.pa1 = u2; o.pa2 = u3; o.pa3 = u3 * u2;
}

__global__ __launch_bounds__(THREADS, 8)
void dendrite_kernel(const float* __restrict__ x,  const float* __restrict__ k,
                     const float* __restrict__ w,  const float* __restrict__ q,
                     const float* __restrict__ lin_w, const float* __restrict__ lin_b,
                     float* __restrict__ out)
{
    __shared__ __align__(16) float sA[256];       // -k*w*log2e, [d*8+j]
    __shared__ __align__(16) float sC[256];       //  k*q*log2e, [d*8+j]
    __shared__ __align__(16) float sLW[256];      // LWv: [0]=bias, [v]=lin_w[v-1]
    __shared__ __align__(16) float sX[BPB * 8];   // 64 floats

    const int tid = threadIdx.x;
    const float LOG2E = 1.4426950408889634f;

    // ---- cooperative load / precompute (128 threads cover 256 entries) ----
#pragma unroll
    for (int i = tid; i < 256; i += THREADS) {
        float kk = k[i] * LOG2E;
        sA[i] = -kk * w[i];
        sC[i] =  kk * q[i];
        sLW[i] = (i == 0) ? lin_b[0] : lin_w[i - 1];
    }
    if (tid < BPB * 8) sX[tid] = x[blockIdx.x * (BPB * 8) + tid];
    __syncthreads();

    const int d  = tid & 31;   // lane = d
    const int bl = tid >> 5;   // warp = local b-pair index

    // per-d sigmoid coefficients (shared by both b's of this thread)
    float4 a0 = *(const float4*)(sA + d * 8);
    float4 a1 = *(const float4*)(sA + d * 8 + 4);
    float4 c0 = *(const float4*)(sC + d * 8);
    float4 c1 = *(const float4*)(sC + d * 8 + 4);
    float av[8] = {a0.x, a0.y, a0.z, a0.w, a1.x, a1.y, a1.z, a1.w};
    float cv[8] = {c0.x, c0.y, c0.z, c0.w, c1.x, c1.y, c1.z, c1.w};

    // two x rows (warp-broadcast shared reads)
    float4 xa0 = *(const float4*)(sX + bl * 16);
    float4 xb0 = *(const float4*)(sX + bl * 16 + 4);
    float4 xa1 = *(const float4*)(sX + bl * 16 + 8);
    float4 xb1 = *(const float4*)(sX + bl * 16 + 12);
    float xv0[8] = {xa0.x, xa0.y, xa0.z, xa0.w, xb0.x, xb0.y, xb0.z, xb0.w};
    float xv1[8] = {xa1.x, xa1.y, xa1.z, xa1.w, xb1.x, xb1.y, xb1.z, xb1.w};

    // ---- sigmoids: s = 1/(1 + 2^(A*x + C)), A=-k*w*log2e, C=k*q*log2e ----
    float s0[8], s1[8];
#pragma unroll
    for (int j = 0; j < 8; j++) {
        s0[j] = rcp_(1.0f + ex2_(fmaf(av[j], xv0[j], cv[j])));
        s1[j] = rcp_(1.0f + ex2_(fmaf(av[j], xv1[j], cv[j])));
    }

    Chain p0, p1;
    build_chain(s0, p0);
    build_chain(s1, p1);

    // ---- bilinear: one LW stream feeds two independent packed dot chains ----
    const uint32_t lwbase = (uint32_t)__cvta_generic_to_shared(sLW);
    unsigned long long Y0 = 0ull, Y1 = 0ull;
#pragma unroll
    for (int hi = 0; hi < 16; hi++) {
        const int h0 = hi & 3, h1 = hi >> 2;
        unsigned long long l0, l1, l2, l3, l4, l5, l6, l7;
        uint32_t a = lwbase + hi * 64;
        asm("ld.shared.v2.u64 {%0,%1}, [%2];" : "=l"(l0), "=l"(l1) : "r"(a));
        asm("ld.shared.v2.u64 {%0,%1}, [%2];" : "=l"(l2), "=l"(l3) : "r"(a + 16));
        asm("ld.shared.v2.u64 {%0,%1}, [%2];" : "=l"(l4), "=l"(l5) : "r"(a + 32));
        asm("ld.shared.v2.u64 {%0,%1}, [%2];" : "=l"(l6), "=l"(l7) : "r"(a + 48));

        unsigned long long acc0 = mul2_(l0, p0.plo2[0]);
        unsigned long long acc1 = mul2_(l0, p1.plo2[0]);
        acc0 = fma2(l1, p0.plo2[1], acc0);  acc1 = fma2(l1, p1.plo2[1], acc1);
        acc0 = fma2(l2, p0.plo2[2], acc0);  acc1 = fma2(l2, p1.plo2[2], acc1);
        acc0 = fma2(l3, p0.plo2[3], acc0);  acc1 = fma2(l3, p1.plo2[3], acc1);
        acc0 = fma2(l4, p0.plo2[4], acc0);  acc1 = fma2(l4, p1.plo2[4], acc1);
        acc0 = fma2(l5, p0.plo2[5], acc0);  acc1 = fma2(l5, p1.plo2[5], acc1);
        acc0 = fma2(l6, p0.plo2[6], acc0);  acc1 = fma2(l6, p1.plo2[6], acc1);
        acc0 = fma2(l7, p0.plo2[7], acc0);  acc1 = fma2(l7, p1.plo2[7], acc1);

        // Phi[hi] = PA[h1]*PB[h0]; PA[0]=PB[0]=1 fold at compile time.
        // Packed-phi accumulation: Y += (phi,phi) * acc, unpack only once at end.
        if (hi == 0) {
            Y0 = acc0;
            Y1 = acc1;
        } else {
            float f0 = sel4(p0.pa1, p0.pa2, p0.pa3, h1) * sel4(p0.pb1, p0.pb2, p0.pb3, h0);
            float f1 = sel4(p1.pa1, p1.pa2, p1.pa3, h1) * sel4(p1.pb1, p1.pb2, p1.pb3, h0);
            Y0 = fma2(pk2(f0, f0), acc0, Y0);
            Y1 = fma2(pk2(f1, f1), acc1, Y1);
        }
    }

    float y0l, y0h, y1l, y1h;
    upk2(Y0, y0l, y0h);
    upk2(Y1, y1l, y1h);

    const int b0 = blockIdx.x * BPB + bl * 2;
    out[(b0 + 0) * 32 + d] = y0l + y0h;   // output layout [B,1,D] -> b*D + d
    out[(b0 + 1) * 32 + d] = y1l + y1h;
}

extern "C" void kernel_launch(void* const* d_in, const int* in_sizes, int n_in,
                              void* d_out, int out_size)
{
    const float* x     = (const float*)d_in[0];
    const float* k     = (const float*)d_in[1];
    const float* w     = (const float*)d_in[2];
    const float* q     = (const float*)d_in[3];
    // d_in[4] = mask: unused — its structure (binary expansion of 1..255,
    // MSB-first) is baked into the subset-product formulation above.
    const float* lin_w = (const float*)d_in[5];
    const float* lin_b = (const float*)d_in[6];
    float* out = (float*)d_out;

    // B=8192, D=32; 8 b's per 128-thread block -> 1024 blocks, 2 (b,d)/thread.
    // launch_bounds(128,8): regs<=64 -> 8 blocks/SM -> 8 warps/SMSP, and 1024
    // small blocks give ~1% SM load imbalance (vs 15% at grid 256).
    dendrite_kernel<<<8192 / BPB, THREADS>>>(x, k, w, q, lin_w, lin_b, out);
}